// round 7
// baseline (speedup 1.0000x reference)
#include <cuda_runtime.h>
#include <cuda_bf16.h>
#include <cstdint>

#define N_NODES 262144
#define C 64
#define K 16
#define NCLS 40

#define WARPS 16
#define THREADS (WARPS * 32)
#define NODES_PER_BLOCK 128
#define NODES_PER_WARP 8

// ---- A-fragment feat storage: 16 ktiles, each 128 rows x 8 cols bf16 = 2048B, pad to 2064 ----
#define KTS 2064

// ---- dynamic smem layout (bytes): A hi | A lo only (B + bias live in L1 via ldg) ----
#define SM_F_HI 0
#define SM_F_LO 33024
#define SMEM_BYTES 66176            // 2*33024 + pad; 3 blocks/SM = 198.5KB <= 228KB

#define B_IMG_U16 5120              // one image: 8 kt2 * 5 nt * 32 lanes * 4 u16

// ---- device scratch (allocation-free rule) ----
__device__ __align__(256) static float d_h[N_NODES * C];       // 64 MB
__device__ static float d_bf[NCLS];
__device__ __align__(16) static uint16_t d_Bfrag[2 * B_IMG_U16]; // k16-paired B frags hi|lo
__device__ static int d_idx64;

// ---------- helpers ----------
__device__ __forceinline__ uint32_t pack_bf2(float a, float b, float& ra, float& rb) {
    __nv_bfloat162 t = __floats2bfloat162_rn(a, b);
    ra = a - __bfloat162float(__low2bfloat16(t));
    rb = b - __bfloat162float(__high2bfloat16(t));
    return *reinterpret_cast<uint32_t*>(&t);
}
__device__ __forceinline__ uint32_t pack_bf2n(float a, float b) {
    __nv_bfloat162 t = __floats2bfloat162_rn(a, b);
    return *reinterpret_cast<uint32_t*>(&t);
}
__device__ __forceinline__ void mma16(float* c, uint32_t a0, uint32_t a1, uint32_t a2,
                                      uint32_t a3, uint32_t b0, uint32_t b1) {
    asm volatile("mma.sync.aligned.m16n8k16.row.col.f32.bf16.bf16.f32 "
                 "{%0,%1,%2,%3}, {%4,%5,%6,%7}, {%8,%9}, {%0,%1,%2,%3};"
                 : "+f"(c[0]), "+f"(c[1]), "+f"(c[2]), "+f"(c[3])
                 : "r"(a0), "r"(a1), "r"(a2), "r"(a3), "r"(b0), "r"(b1));
}

// ---------- kernel 0: idx dtype detect ----------
__global__ void detect_idx_kernel(const unsigned int* __restrict__ w) {
    __shared__ int any;
    if (threadIdx.x == 0) any = 0;
    __syncthreads();
    if (w[2 * threadIdx.x + 1] != 0u) any = 1;
    __syncthreads();
    if (threadIdx.x == 0) d_idx64 = (any ? 0 : 1);
}

// ---------- kernel 1: CPE depthwise conv + residual ----------
__global__ void cpe_kernel(const float4* __restrict__ x4,
                           const float* __restrict__ cw,
                           const float* __restrict__ cb) {
    const int idx = blockIdx.x * blockDim.x + threadIdx.x;
    const int q = idx & 15;
    const int n0 = (idx >> 4) * 8;
    if (n0 >= N_NODES) return;
    const int c0 = q * 4;
    const float w0x = __ldg(cw + (c0+0)*3+0), w1x = __ldg(cw + (c0+0)*3+1), w2x = __ldg(cw + (c0+0)*3+2);
    const float w0y = __ldg(cw + (c0+1)*3+0), w1y = __ldg(cw + (c0+1)*3+1), w2y = __ldg(cw + (c0+1)*3+2);
    const float w0z = __ldg(cw + (c0+2)*3+0), w1z = __ldg(cw + (c0+2)*3+1), w2z = __ldg(cw + (c0+2)*3+2);
    const float w0w = __ldg(cw + (c0+3)*3+0), w1w = __ldg(cw + (c0+3)*3+1), w2w = __ldg(cw + (c0+3)*3+2);
    const float bx = __ldg(cb+c0+0), by = __ldg(cb+c0+1), bz = __ldg(cb+c0+2), bw = __ldg(cb+c0+3);

    const float4 zero = make_float4(0.f, 0.f, 0.f, 0.f);
    float4 a = (n0 > 0) ? x4[(n0 - 1) * 16 + q] : zero;
    float4 b = x4[n0 * 16 + q];
    float4* h4 = reinterpret_cast<float4*>(d_h);
    #pragma unroll
    for (int r = 0; r < 8; ++r) {
        const int n = n0 + r;
        const float4 nx = (n + 1 < N_NODES) ? x4[(n + 1) * 16 + q] : zero;
        float4 o;
        o.x = b.x + (a.x*w0x + b.x*w1x + nx.x*w2x + bx);
        o.y = b.y + (a.y*w0y + b.y*w1y + nx.y*w2y + by);
        o.z = b.z + (a.z*w0z + b.z*w1z + nx.z*w2z + bz);
        o.w = b.w + (a.w*w0w + b.w*w1w + nx.w*w2w + bw);
        h4[n * 16 + q] = o;
        a = b; b = nx;
    }
}

// ---------- kernel 2: fuse grapher into head; emit k16-paired B-fragment images ----------
// W[c][j] = (c<64 ? ow[c][j] : 0) + sum_d gw[c][d]*ow[d][j]
// m16n8k16 B frag: image u16 index = ((kt2*5+nt)*32 + lane)*4 + pairw*2 + half
//   kt2 = c>>4, pairw = (c>>3)&1, nt = j>>3, lane = (j&7)*4 + ((c&7)>>1), half = c&1
__global__ void fuse_w_kernel(const float* __restrict__ gw, const float* __restrict__ gb,
                              const float* __restrict__ ow, const float* __restrict__ ob) {
    int t = blockIdx.x * blockDim.x + threadIdx.x;
    if (t < 2 * C * NCLS) {
        int c = t / NCLS, j = t % NCLS;
        float acc = (c < C) ? ow[c * NCLS + j] : 0.f;
        #pragma unroll 8
        for (int d = 0; d < C; ++d) acc += gw[c * C + d] * ow[d * NCLS + j];
        const int kt2 = c >> 4, pairw = (c >> 3) & 1, nt = j >> 3;
        const int lane = (j & 7) * 4 + ((c & 7) >> 1);
        const int idx = ((kt2 * 5 + nt) * 32 + lane) * 4 + pairw * 2 + (c & 1);
        __nv_bfloat16 hi = __float2bfloat16(acc);
        __nv_bfloat16 lo = __float2bfloat16(acc - __bfloat162float(hi));
        d_Bfrag[idx]             = *reinterpret_cast<uint16_t*>(&hi);
        d_Bfrag[idx + B_IMG_U16] = *reinterpret_cast<uint16_t*>(&lo);
    } else if (t < 2 * C * NCLS + NCLS) {
        int j = t - 2 * C * NCLS;
        float acc = ob[j];
        for (int d = 0; d < C; ++d) acc += gb[d] * ow[d * NCLS + j];
        d_bf[j] = acc;
    }
}

// ---------- kernel 3: gather -> A-frag tiles -> mma.sync m16n8k16 -> log_softmax ----------
__global__ __launch_bounds__(THREADS, 3) void main_kernel(const void* __restrict__ nbr,
                                                          float* __restrict__ out) {
    extern __shared__ __align__(16) char smem[];
    const int tid = threadIdx.x;
    const int warp = tid >> 5, lane = tid & 31;
    const float* __restrict__ H = d_h;

    // ---- gather: half-warp = 1 node; lane owns channel quad q = lane&15 ----
    const int nodeBase = blockIdx.x * NODES_PER_BLOCK + warp * NODES_PER_WARP;
    const int is64 = d_idx64;
    const int q = lane & 15;          // channel quad (channels 4q..4q+3)
    const int half = lane >> 4;       // which node of the pair
    const int n0 = nodeBase + half;   // iteration t handles node n0 + 2t

    // hoist neighbor-index loads (4 independent L2-latency loads carry the serial chain)
    int idxs[4];
    if (is64) {
        const long long* p = (const long long*)nbr + (size_t)n0 * K + q;
        #pragma unroll
        for (int t = 0; t < 4; ++t) idxs[t] = (int)p[2 * t * K];
    } else {
        const int* p = (const int*)nbr + n0 * K + q;
        #pragma unroll
        for (int t = 0; t < 4; ++t) idxs[t] = p[2 * t * K];
    }

    const uint32_t baseC = (uint32_t)(q >> 1) * KTS
                         + (uint32_t)((warp >> 1) * 2 + (warp & 1)) * 128
                         + (uint32_t)(half * 4 + (q & 1) * 2) * 4;

    #pragma unroll
    for (int t = 0; t < 4; ++t) {
        const int myj = idxs[t];
        const float4 hv = *(const float4*)(H + (n0 + 2 * t) * C + q * 4);
        float4 m0 = make_float4(-3.402823466e38f, -3.402823466e38f,
                                -3.402823466e38f, -3.402823466e38f);
        float4 m1 = m0;
        #pragma unroll
        for (int k = 0; k < K; k += 2) {
            const int j0 = __shfl_sync(0xffffffffu, myj, k, 16);
            const int j1 = __shfl_sync(0xffffffffu, myj, k + 1, 16);
            const float4 x0 = __ldg((const float4*)(H + j0 * C + q * 4));
            const float4 x1 = __ldg((const float4*)(H + j1 * C + q * 4));
            m0.x = fmaxf(m0.x, x0.x); m0.y = fmaxf(m0.y, x0.y);
            m0.z = fmaxf(m0.z, x0.z); m0.w = fmaxf(m0.w, x0.w);
            m1.x = fmaxf(m1.x, x1.x); m1.y = fmaxf(m1.y, x1.y);
            m1.z = fmaxf(m1.z, x1.z); m1.w = fmaxf(m1.w, x1.w);
        }
        const float4 rv = make_float4(fmaxf(m0.x, m1.x) - hv.x,
                                      fmaxf(m0.y, m1.y) - hv.y,
                                      fmaxf(m0.z, m1.z) - hv.z,
                                      fmaxf(m0.w, m1.w) - hv.w);

        const uint32_t base = baseC + (uint32_t)t * 32;
        float hl0, hl1, hl2, hl3, rl0, rl1, rl2, rl3;
        uint2 hHi, rHi, hLo, rLo;
        hHi.x = pack_bf2(hv.x, hv.y, hl0, hl1);
        hHi.y = pack_bf2(hv.z, hv.w, hl2, hl3);
        rHi.x = pack_bf2(rv.x, rv.y, rl0, rl1);
        rHi.y = pack_bf2(rv.z, rv.w, rl2, rl3);
        hLo.x = pack_bf2n(hl0, hl1);  hLo.y = pack_bf2n(hl2, hl3);
        rLo.x = pack_bf2n(rl0, rl1);  rLo.y = pack_bf2n(rl2, rl3);
        *(uint2*)(smem + SM_F_HI + base)           = hHi;          // ktiles 0..7  (h)
        *(uint2*)(smem + SM_F_HI + 8 * KTS + base) = rHi;          // ktiles 8..15 (rel)
        *(uint2*)(smem + SM_F_LO + base)           = hLo;
        *(uint2*)(smem + SM_F_LO + 8 * KTS + base) = rLo;
    }
    __syncthreads();

    // ---- MMA: warps 0-7, m16n8k16; B frags via ldg (L1-resident, 20KB) ----
    float lg[2][10];
    float lseA = 0.f, lseB = 0.f;
    if (warp < 8) {
        float acc[5][4];
        #pragma unroll
        for (int nt = 0; nt < 5; ++nt)
            #pragma unroll
            for (int p = 0; p < 4; ++p) acc[nt][p] = 0.f;

        const char* fh = smem + SM_F_HI + (warp * 2) * 128 + lane * 4;
        const char* fl = smem + SM_F_LO + (warp * 2) * 128 + lane * 4;
        const uint2* Bh = reinterpret_cast<const uint2*>(d_Bfrag) + lane;
        const uint2* Bl = Bh + B_IMG_U16 / 4;
        #pragma unroll
        for (int kt2 = 0; kt2 < 8; ++kt2) {
            const uint32_t a0h = *(const uint32_t*)(fh + (2 * kt2) * KTS);
            const uint32_t a1h = *(const uint32_t*)(fh + (2 * kt2) * KTS + 128);
            const uint32_t a2h = *(const uint32_t*)(fh + (2 * kt2 + 1) * KTS);
            const uint32_t a3h = *(const uint32_t*)(fh + (2 * kt2 + 1) * KTS + 128);
            const uint32_t a0l = *(const uint32_t*)(fl + (2 * kt2) * KTS);
            const uint32_t a1l = *(const uint32_t*)(fl + (2 * kt2) * KTS + 128);
            const uint32_t a2l = *(const uint32_t*)(fl + (2 * kt2 + 1) * KTS);
            const uint32_t a3l = *(const uint32_t*)(fl + (2 * kt2 + 1) * KTS + 128);
            #pragma unroll
            for (int nt = 0; nt < 5; ++nt) {
                const uint2 wh = __ldg(Bh + (kt2 * 5 + nt) * 32);
                const uint2 wl = __ldg(Bl + (kt2 * 5 + nt) * 32);
                mma16(acc[nt], a0h, a1h, a2h, a3h, wh.x, wh.y);
                mma16(acc[nt], a0h, a1h, a2h, a3h, wl.x, wl.y);
                mma16(acc[nt], a0l, a1l, a2l, a3l, wh.x, wh.y);
            }
        }

        #pragma unroll
        for (int nt = 0; nt < 5; ++nt) {
            const float2 b = __ldg((const float2*)(d_bf + nt * 8 + (lane & 3) * 2));
            lg[0][2 * nt]     = acc[nt][0] + b.x;
            lg[0][2 * nt + 1] = acc[nt][1] + b.y;
            lg[1][2 * nt]     = acc[nt][2] + b.x;
            lg[1][2 * nt + 1] = acc[nt][3] + b.y;
        }
        float mA = lg[0][0], mB = lg[1][0];
        #pragma unroll
        for (int i = 1; i < 10; ++i) { mA = fmaxf(mA, lg[0][i]); mB = fmaxf(mB, lg[1][i]); }
        mA = fmaxf(mA, __shfl_xor_sync(0xffffffffu, mA, 1));
        mA = fmaxf(mA, __shfl_xor_sync(0xffffffffu, mA, 2));
        mB = fmaxf(mB, __shfl_xor_sync(0xffffffffu, mB, 1));
        mB = fmaxf(mB, __shfl_xor_sync(0xffffffffu, mB, 2));
        float sA = 0.f, sB = 0.f;
        #pragma unroll
        for (int i = 0; i < 10; ++i) { sA += __expf(lg[0][i] - mA); sB += __expf(lg[1][i] - mB); }
        sA += __shfl_xor_sync(0xffffffffu, sA, 1);
        sA += __shfl_xor_sync(0xffffffffu, sA, 2);
        sB += __shfl_xor_sync(0xffffffffu, sB, 1);
        sB += __shfl_xor_sync(0xffffffffu, sB, 2);
        lseA = mA + __logf(sA);
        lseB = mB + __logf(sB);
    }
    __syncthreads();   // MMA warps done reading feat; safe to reuse as staging

    // ---- staging writes (warps 0-7): [128 nodes][stride 42] floats ----
    float* stag = reinterpret_cast<float*>(smem);
    if (warp < 8) {
        const int rA = 16 * warp + (lane >> 2);
        const int col = (lane & 3) * 2;
        #pragma unroll
        for (int nt = 0; nt < 5; ++nt) {
            float2 oA, oB;
            oA.x = lg[0][2 * nt]     - lseA;
            oA.y = lg[0][2 * nt + 1] - lseA;
            oB.x = lg[1][2 * nt]     - lseB;
            oB.y = lg[1][2 * nt + 1] - lseB;
            *(float2*)(stag + rA * 42 + nt * 8 + col)       = oA;
            *(float2*)(stag + (rA + 8) * 42 + nt * 8 + col) = oB;
        }
    }
    __syncthreads();

    // ---- coalesced output copy: thread -> (node = tid/4, class-quarter) ----
    {
        const int node = tid >> 2;
        const int jb = (tid & 3) * 10;
        const float* srow = stag + node * 42 + jb;
        float* drow = out + (size_t)blockIdx.x * NODES_PER_BLOCK * NCLS + node * NCLS + jb;
        #pragma unroll
        for (int p = 0; p < 5; ++p)
            ((float2*)drow)[p] = ((const float2*)srow)[p];
    }
}

extern "C" void kernel_launch(void* const* d_in, const int* in_sizes, int n_in,
                              void* d_out, int out_size) {
    const float* x  = (const float*)d_in[0];
    const void*  nb = d_in[1];
    const float* cw = (const float*)d_in[2];
    const float* cb = (const float*)d_in[3];
    const float* gw = (const float*)d_in[4];
    const float* gb = (const float*)d_in[5];
    const float* ow = (const float*)d_in[6];
    const float* ob = (const float*)d_in[7];
    float* out = (float*)d_out;

    cudaFuncSetAttribute(main_kernel, cudaFuncAttributeMaxDynamicSharedMemorySize, SMEM_BYTES);

    detect_idx_kernel<<<1, 256>>>((const unsigned int*)nb);
    cpe_kernel<<<(N_NODES / 8 * 16 + 255) / 256, 256>>>((const float4*)x, cw, cb);
    fuse_w_kernel<<<(2 * C * NCLS + NCLS + 127) / 128, 128>>>(gw, gb, ow, ob);
    main_kernel<<<N_NODES / NODES_PER_BLOCK, THREADS, SMEM_BYTES>>>(nb, out);
}

// round 8
// speedup vs baseline: 1.6353x; 1.6353x over previous
#include <cuda_runtime.h>
#include <cuda_bf16.h>
#include <cstdint>

#define N_NODES 262144
#define C 64
#define K 16
#define NCLS 40

#define WARPS 16
#define THREADS (WARPS * 32)
#define NODES_PER_BLOCK 128
#define NODES_PER_WARP 8

// ---- A-fragment feat storage: 16 ktiles, each 128 rows x 8 cols bf16 = 2048B, pad to 2064 ----
#define KTS 2064

// ---- dynamic smem layout (bytes) ----
#define SM_F_HI 0
#define SM_F_LO 33024
#define SM_B    66048               // k16-paired B frag images: hi (10240) then lo (10240)
#define SM_BIAS 86528               // 40 floats
#define SMEM_BYTES 86688

#define B_IMG_U16 5120              // one image: 8 kt2 * 5 nt * 32 lanes * 4 u16 = 20480B/2

// ---- device scratch (allocation-free rule) ----
__device__ __align__(256) static float d_h[N_NODES * C];       // 64 MB
__device__ static float d_bf[NCLS];
__device__ __align__(16) static uint16_t d_Bfrag[2 * B_IMG_U16]; // k16-paired B frags hi|lo
__device__ static int d_idx64;

// ---------- helpers ----------
__device__ __forceinline__ uint32_t pack_bf2(float a, float b, float& ra, float& rb) {
    __nv_bfloat162 t = __floats2bfloat162_rn(a, b);
    ra = a - __bfloat162float(__low2bfloat16(t));
    rb = b - __bfloat162float(__high2bfloat16(t));
    return *reinterpret_cast<uint32_t*>(&t);
}
__device__ __forceinline__ uint32_t pack_bf2n(float a, float b) {
    __nv_bfloat162 t = __floats2bfloat162_rn(a, b);
    return *reinterpret_cast<uint32_t*>(&t);
}
__device__ __forceinline__ void mma16(float* c, uint32_t a0, uint32_t a1, uint32_t a2,
                                      uint32_t a3, uint32_t b0, uint32_t b1) {
    asm volatile("mma.sync.aligned.m16n8k16.row.col.f32.bf16.bf16.f32 "
                 "{%0,%1,%2,%3}, {%4,%5,%6,%7}, {%8,%9}, {%0,%1,%2,%3};"
                 : "+f"(c[0]), "+f"(c[1]), "+f"(c[2]), "+f"(c[3])
                 : "r"(a0), "r"(a1), "r"(a2), "r"(a3), "r"(b0), "r"(b1));
}

// ---------- kernel 0: idx dtype detect ----------
__global__ void detect_idx_kernel(const unsigned int* __restrict__ w) {
    __shared__ int any;
    if (threadIdx.x == 0) any = 0;
    __syncthreads();
    if (w[2 * threadIdx.x + 1] != 0u) any = 1;
    __syncthreads();
    if (threadIdx.x == 0) d_idx64 = (any ? 0 : 1);
}

// ---------- kernel 1: CPE depthwise conv + residual ----------
__global__ void cpe_kernel(const float4* __restrict__ x4,
                           const float* __restrict__ cw,
                           const float* __restrict__ cb) {
    const int idx = blockIdx.x * blockDim.x + threadIdx.x;
    const int q = idx & 15;
    const int n0 = (idx >> 4) * 8;
    if (n0 >= N_NODES) return;
    const int c0 = q * 4;
    const float w0x = __ldg(cw + (c0+0)*3+0), w1x = __ldg(cw + (c0+0)*3+1), w2x = __ldg(cw + (c0+0)*3+2);
    const float w0y = __ldg(cw + (c0+1)*3+0), w1y = __ldg(cw + (c0+1)*3+1), w2y = __ldg(cw + (c0+1)*3+2);
    const float w0z = __ldg(cw + (c0+2)*3+0), w1z = __ldg(cw + (c0+2)*3+1), w2z = __ldg(cw + (c0+2)*3+2);
    const float w0w = __ldg(cw + (c0+3)*3+0), w1w = __ldg(cw + (c0+3)*3+1), w2w = __ldg(cw + (c0+3)*3+2);
    const float bx = __ldg(cb+c0+0), by = __ldg(cb+c0+1), bz = __ldg(cb+c0+2), bw = __ldg(cb+c0+3);

    const float4 zero = make_float4(0.f, 0.f, 0.f, 0.f);
    float4 a = (n0 > 0) ? x4[(n0 - 1) * 16 + q] : zero;
    float4 b = x4[n0 * 16 + q];
    float4* h4 = reinterpret_cast<float4*>(d_h);
    #pragma unroll
    for (int r = 0; r < 8; ++r) {
        const int n = n0 + r;
        const float4 nx = (n + 1 < N_NODES) ? x4[(n + 1) * 16 + q] : zero;
        float4 o;
        o.x = b.x + (a.x*w0x + b.x*w1x + nx.x*w2x + bx);
        o.y = b.y + (a.y*w0y + b.y*w1y + nx.y*w2y + by);
        o.z = b.z + (a.z*w0z + b.z*w1z + nx.z*w2z + bz);
        o.w = b.w + (a.w*w0w + b.w*w1w + nx.w*w2w + bw);
        h4[n * 16 + q] = o;
        a = b; b = nx;
    }
}

// ---------- kernel 2: fuse grapher into head; emit k16-paired B-fragment images ----------
// W[c][j] = (c<64 ? ow[c][j] : 0) + sum_d gw[c][d]*ow[d][j]
// m16n8k16 B frag: u16 index = ((kt2*5+nt)*32 + lane)*4 + pairw*2 + half
//   kt2 = c>>4, pairw = (c>>3)&1, nt = j>>3, lane = (j&7)*4 + ((c&7)>>1), half = c&1
__global__ void fuse_w_kernel(const float* __restrict__ gw, const float* __restrict__ gb,
                              const float* __restrict__ ow, const float* __restrict__ ob) {
    int t = blockIdx.x * blockDim.x + threadIdx.x;
    if (t < 2 * C * NCLS) {
        int c = t / NCLS, j = t % NCLS;
        float acc = (c < C) ? ow[c * NCLS + j] : 0.f;
        #pragma unroll 8
        for (int d = 0; d < C; ++d) acc += gw[c * C + d] * ow[d * NCLS + j];
        const int kt2 = c >> 4, pairw = (c >> 3) & 1, nt = j >> 3;
        const int lane = (j & 7) * 4 + ((c & 7) >> 1);
        const int idx = ((kt2 * 5 + nt) * 32 + lane) * 4 + pairw * 2 + (c & 1);
        __nv_bfloat16 hi = __float2bfloat16(acc);
        __nv_bfloat16 lo = __float2bfloat16(acc - __bfloat162float(hi));
        d_Bfrag[idx]             = *reinterpret_cast<uint16_t*>(&hi);
        d_Bfrag[idx + B_IMG_U16] = *reinterpret_cast<uint16_t*>(&lo);
    } else if (t < 2 * C * NCLS + NCLS) {
        int j = t - 2 * C * NCLS;
        float acc = ob[j];
        for (int d = 0; d < C; ++d) acc += gb[d] * ow[d * NCLS + j];
        d_bf[j] = acc;
    }
}

// ---------- kernel 3: gather -> A-frag tiles -> mma.sync m16n8k16 -> log_softmax ----------
__global__ __launch_bounds__(THREADS, 2) void main_kernel(const void* __restrict__ nbr,
                                                          float* __restrict__ out) {
    extern __shared__ __align__(16) char smem[];
    const int tid = threadIdx.x;
    const int warp = tid >> 5, lane = tid & 31;
    const float* __restrict__ H = d_h;

    // stage k16-paired B fragment images (20480 B) + bias
    {
        const int4* src = reinterpret_cast<const int4*>(d_Bfrag);
        int4* dst = reinterpret_cast<int4*>(smem + SM_B);
        #pragma unroll
        for (int i = tid; i < 20480 / 16; i += THREADS) dst[i] = src[i];
        if (tid < NCLS) *(float*)(smem + SM_BIAS + 4 * tid) = d_bf[tid];
    }

    // ---- gather: half-warp = 1 node; lane owns channel quad q = lane&15 (R6-identical) ----
    const int nodeBase = blockIdx.x * NODES_PER_BLOCK + warp * NODES_PER_WARP;
    const int is64 = d_idx64;
    const int q = lane & 15;
    const int half = lane >> 4;
    const int n0 = nodeBase + half;

    int idxs[4];
    if (is64) {
        const long long* p = (const long long*)nbr + (size_t)n0 * K + q;
        #pragma unroll
        for (int t = 0; t < 4; ++t) idxs[t] = (int)p[2 * t * K];
    } else {
        const int* p = (const int*)nbr + n0 * K + q;
        #pragma unroll
        for (int t = 0; t < 4; ++t) idxs[t] = p[2 * t * K];
    }
    float4 hvs[4];
    {
        const float4* p = (const float4*)(H + n0 * C) + q;
        #pragma unroll
        for (int t = 0; t < 4; ++t) hvs[t] = p[2 * t * (C / 4)];
    }

    const uint32_t baseC = (uint32_t)(q >> 1) * KTS
                         + (uint32_t)((warp >> 1) * 2 + (warp & 1)) * 128
                         + (uint32_t)(half * 4 + (q & 1) * 2) * 4;

    #pragma unroll
    for (int t = 0; t < 4; ++t) {
        const int myj = idxs[t];
        const float4 hv = hvs[t];
        float4 m0 = make_float4(-3.402823466e38f, -3.402823466e38f,
                                -3.402823466e38f, -3.402823466e38f);
        float4 m1 = m0;
        #pragma unroll
        for (int k = 0; k < K; k += 2) {
            const int j0 = __shfl_sync(0xffffffffu, myj, k, 16);
            const int j1 = __shfl_sync(0xffffffffu, myj, k + 1, 16);
            const float4 x0 = __ldg((const float4*)(H + j0 * C + q * 4));
            const float4 x1 = __ldg((const float4*)(H + j1 * C + q * 4));
            m0.x = fmaxf(m0.x, x0.x); m0.y = fmaxf(m0.y, x0.y);
            m0.z = fmaxf(m0.z, x0.z); m0.w = fmaxf(m0.w, x0.w);
            m1.x = fmaxf(m1.x, x1.x); m1.y = fmaxf(m1.y, x1.y);
            m1.z = fmaxf(m1.z, x1.z); m1.w = fmaxf(m1.w, x1.w);
        }
        const float4 rv = make_float4(fmaxf(m0.x, m1.x) - hv.x,
                                      fmaxf(m0.y, m1.y) - hv.y,
                                      fmaxf(m0.z, m1.z) - hv.z,
                                      fmaxf(m0.w, m1.w) - hv.w);

        const uint32_t base = baseC + (uint32_t)t * 32;
        float hl0, hl1, hl2, hl3, rl0, rl1, rl2, rl3;
        uint2 hHi, rHi, hLo, rLo;
        hHi.x = pack_bf2(hv.x, hv.y, hl0, hl1);
        hHi.y = pack_bf2(hv.z, hv.w, hl2, hl3);
        rHi.x = pack_bf2(rv.x, rv.y, rl0, rl1);
        rHi.y = pack_bf2(rv.z, rv.w, rl2, rl3);
        hLo.x = pack_bf2n(hl0, hl1);  hLo.y = pack_bf2n(hl2, hl3);
        rLo.x = pack_bf2n(rl0, rl1);  rLo.y = pack_bf2n(rl2, rl3);
        *(uint2*)(smem + SM_F_HI + base)           = hHi;          // ktiles 0..7  (h)
        *(uint2*)(smem + SM_F_HI + 8 * KTS + base) = rHi;          // ktiles 8..15 (rel)
        *(uint2*)(smem + SM_F_LO + base)           = hLo;
        *(uint2*)(smem + SM_F_LO + 8 * KTS + base) = rLo;
    }
    __syncthreads();

    // ---- MMA: warps 0-7, m16n8k16, smem-staged B; then direct-STG epilogue ----
    if (warp < 8) {
        float acc[5][4];
        #pragma unroll
        for (int nt = 0; nt < 5; ++nt)
            #pragma unroll
            for (int p = 0; p < 4; ++p) acc[nt][p] = 0.f;

        const char* fh = smem + SM_F_HI + (warp * 2) * 128 + lane * 4;
        const char* fl = smem + SM_F_LO + (warp * 2) * 128 + lane * 4;
        const uint2* Bh = reinterpret_cast<const uint2*>(smem + SM_B) + lane;
        const uint2* Bl = Bh + 10240 / 8;
        #pragma unroll
        for (int kt2 = 0; kt2 < 8; ++kt2) {
            const uint32_t a0h = *(const uint32_t*)(fh + (2 * kt2) * KTS);
            const uint32_t a1h = *(const uint32_t*)(fh + (2 * kt2) * KTS + 128);
            const uint32_t a2h = *(const uint32_t*)(fh + (2 * kt2 + 1) * KTS);
            const uint32_t a3h = *(const uint32_t*)(fh + (2 * kt2 + 1) * KTS + 128);
            const uint32_t a0l = *(const uint32_t*)(fl + (2 * kt2) * KTS);
            const uint32_t a1l = *(const uint32_t*)(fl + (2 * kt2) * KTS + 128);
            const uint32_t a2l = *(const uint32_t*)(fl + (2 * kt2 + 1) * KTS);
            const uint32_t a3l = *(const uint32_t*)(fl + (2 * kt2 + 1) * KTS + 128);
            #pragma unroll
            for (int nt = 0; nt < 5; ++nt) {
                const uint2 wh = Bh[(kt2 * 5 + nt) * 32];
                const uint2 wl = Bl[(kt2 * 5 + nt) * 32];
                mma16(acc[nt], a0h, a1h, a2h, a3h, wh.x, wh.y);
                mma16(acc[nt], a0h, a1h, a2h, a3h, wl.x, wl.y);
                mma16(acc[nt], a0l, a1l, a2l, a3l, wh.x, wh.y);
            }
        }

        // bias + per-row log_softmax (rows: rA = 16w + lane/4, rB = rA + 8)
        float lg[2][10];
        #pragma unroll
        for (int nt = 0; nt < 5; ++nt) {
            const float b0 = *(const float*)(smem + SM_BIAS + (nt * 8 + (lane & 3) * 2) * 4);
            const float b1 = *(const float*)(smem + SM_BIAS + (nt * 8 + (lane & 3) * 2 + 1) * 4);
            lg[0][2 * nt]     = acc[nt][0] + b0;
            lg[0][2 * nt + 1] = acc[nt][1] + b1;
            lg[1][2 * nt]     = acc[nt][2] + b0;
            lg[1][2 * nt + 1] = acc[nt][3] + b1;
        }
        float mA = lg[0][0], mB = lg[1][0];
        #pragma unroll
        for (int i = 1; i < 10; ++i) { mA = fmaxf(mA, lg[0][i]); mB = fmaxf(mB, lg[1][i]); }
        mA = fmaxf(mA, __shfl_xor_sync(0xffffffffu, mA, 1));
        mA = fmaxf(mA, __shfl_xor_sync(0xffffffffu, mA, 2));
        mB = fmaxf(mB, __shfl_xor_sync(0xffffffffu, mB, 1));
        mB = fmaxf(mB, __shfl_xor_sync(0xffffffffu, mB, 2));
        float sA = 0.f, sB = 0.f;
        #pragma unroll
        for (int i = 0; i < 10; ++i) { sA += __expf(lg[0][i] - mA); sB += __expf(lg[1][i] - mB); }
        sA += __shfl_xor_sync(0xffffffffu, sA, 1);
        sA += __shfl_xor_sync(0xffffffffu, sA, 2);
        sB += __shfl_xor_sync(0xffffffffu, sB, 1);
        sB += __shfl_xor_sync(0xffffffffu, sB, 2);
        const float lseA = mA + __logf(sA);
        const float lseB = mB + __logf(sB);

        // direct global stores: rows rA and rA+8, cols nt*8 + (lane&3)*2 (+1)
        const int rA = 16 * warp + (lane >> 2);
        float* rowA = out + ((size_t)blockIdx.x * NODES_PER_BLOCK + rA) * NCLS + (lane & 3) * 2;
        float* rowB = rowA + 8 * NCLS;
        #pragma unroll
        for (int nt = 0; nt < 5; ++nt) {
            float2 oA, oB;
            oA.x = lg[0][2 * nt]     - lseA;
            oA.y = lg[0][2 * nt + 1] - lseA;
            oB.x = lg[1][2 * nt]     - lseB;
            oB.y = lg[1][2 * nt + 1] - lseB;
            *(float2*)(rowA + nt * 8) = oA;
            *(float2*)(rowB + nt * 8) = oB;
        }
    }
}

extern "C" void kernel_launch(void* const* d_in, const int* in_sizes, int n_in,
                              void* d_out, int out_size) {
    const float* x  = (const float*)d_in[0];
    const void*  nb = d_in[1];
    const float* cw = (const float*)d_in[2];
    const float* cb = (const float*)d_in[3];
    const float* gw = (const float*)d_in[4];
    const float* gb = (const float*)d_in[5];
    const float* ow = (const float*)d_in[6];
    const float* ob = (const float*)d_in[7];
    float* out = (float*)d_out;

    cudaFuncSetAttribute(main_kernel, cudaFuncAttributeMaxDynamicSharedMemorySize, SMEM_BYTES);

    detect_idx_kernel<<<1, 256>>>((const unsigned int*)nb);
    cpe_kernel<<<(N_NODES / 8 * 16 + 255) / 256, 256>>>((const float4*)x, cw, cb);
    fuse_w_kernel<<<(2 * C * NCLS + NCLS + 127) / 128, 128>>>(gw, gb, ow, ob);
    main_kernel<<<N_NODES / NODES_PER_BLOCK, THREADS, SMEM_BYTES>>>(nb, out);
}